// round 5
// baseline (speedup 1.0000x reference)
#include <cuda_runtime.h>
#include <cuda_bf16.h>

// Problem constants (fixed by the dataset)
#define NN 50000
#define EE 850000
#define DIN 128
#define D1 64
#define H1 8
#define D2 16
#define NBMAX 256

// ---------------- scratch (__device__ globals; zero-initialized at load) -------
__device__ float    g_z1[NN * D1];
__device__ float    g_as1[NN * H1];
__device__ float    g_ad1[NN * H1];
__device__ unsigned g_ms1[H1];
__device__ unsigned g_md1[H1];
__device__ int      g_counts[NN];     // self-cleaned by scanC each call
__device__ int      g_rowptr[NN + 1];
__device__ int      g_cursor[NN];
__device__ int      g_csr[EE];
__device__ int      g_bsum[NBMAX];
__device__ float    g_z2[NN * D2];
__device__ float    g_as2[NN];
__device__ float    g_ad2[NN];
__device__ unsigned g_ms2;
__device__ unsigned g_md2;

__device__ __forceinline__ unsigned fenc(float f) {
    unsigned u = __float_as_uint(f);
    return (u & 0x80000000u) ? ~u : (u | 0x80000000u);
}
__device__ __forceinline__ float fdec(unsigned u) {
    return __uint_as_float((u & 0x80000000u) ? (u & 0x7fffffffu) : ~u);
}
__device__ __forceinline__ float leaky(float e) { return e > 0.f ? e : 0.2f * e; }
__device__ __forceinline__ float dot4(float4 a, float4 b) {
    return a.x * b.x + a.y * b.y + a.z * b.z + a.w * b.w;
}

// ---------------- init: zero only the max slots (1 warp) -----------------------
__global__ void init_kernel() {
    int i = threadIdx.x;
    if (i < H1) { g_ms1[i] = 0u; g_md1[i] = 0u; }
    if (i == 0) { g_ms2 = 0u; g_md2 = 0u; }
}

// ---------------- GEMM1: 256-node tile, 4 nodes/thread, k-chunked smem ---------
__global__ __launch_bounds__(256, 2)
void gemm1_kernel(const float* __restrict__ x,
                  const float* __restrict__ W1,
                  const float* __restrict__ a_src1,
                  const float* __restrict__ a_dst1,
                  int N) {
    __shared__ float sX[256 * 33];
    __shared__ float sW[32 * 64];
    __shared__ unsigned sMax[16];
    int t = threadIdx.x;
    if (t < 16) sMax[t] = 0u;
    int base = blockIdx.x << 8;
    int nl = t >> 2;
    int q  = t & 3;

    float4 acc[4][4];
#pragma unroll
    for (int i = 0; i < 4; i++)
#pragma unroll
        for (int j = 0; j < 4; j++) acc[i][j] = make_float4(0.f, 0.f, 0.f, 0.f);

    for (int kc = 0; kc < 4; kc++) {
        __syncthreads();
#pragma unroll
        for (int i = 0; i < 2; i++)
            ((float4*)sW)[t + (i << 8)] =
                __ldg((const float4*)(W1 + (kc << 11)) + t + (i << 8));
#pragma unroll
        for (int i = 0; i < 8; i++) {
            int idx = t + (i << 8);
            int node = idx >> 3, k4 = idx & 7;
            int n = base + node;
            float4 v = make_float4(0.f, 0.f, 0.f, 0.f);
            if (n < N) v = __ldg((const float4*)x + ((size_t)n << 5) + (kc << 3) + k4);
            float* dp = &sX[node * 33 + (k4 << 2)];
            dp[0] = v.x; dp[1] = v.y; dp[2] = v.z; dp[3] = v.w;
        }
        __syncthreads();
#pragma unroll 8
        for (int k = 0; k < 32; k++) {
            const float4* wr = (const float4*)&sW[(k << 6) + (q << 4)];
            float4 w0 = wr[0], w1 = wr[1], w2 = wr[2], w3 = wr[3];
#pragma unroll
            for (int i = 0; i < 4; i++) {
                float xv = sX[(nl + (i << 6)) * 33 + k];
                acc[i][0].x += xv * w0.x; acc[i][0].y += xv * w0.y;
                acc[i][0].z += xv * w0.z; acc[i][0].w += xv * w0.w;
                acc[i][1].x += xv * w1.x; acc[i][1].y += xv * w1.y;
                acc[i][1].z += xv * w1.z; acc[i][1].w += xv * w1.w;
                acc[i][2].x += xv * w2.x; acc[i][2].y += xv * w2.y;
                acc[i][2].z += xv * w2.z; acc[i][2].w += xv * w2.w;
                acc[i][3].x += xv * w3.x; acc[i][3].y += xv * w3.y;
                acc[i][3].z += xv * w3.z; acc[i][3].w += xv * w3.w;
            }
        }
    }

    int h0 = q << 1;
    const float4* As4 = (const float4*)a_src1;
    const float4* Ad4 = (const float4*)a_dst1;
    float4 s0 = __ldg(&As4[h0 * 2]),     s1 = __ldg(&As4[h0 * 2 + 1]);
    float4 s2 = __ldg(&As4[h0 * 2 + 2]), s3 = __ldg(&As4[h0 * 2 + 3]);
    float4 d0 = __ldg(&Ad4[h0 * 2]),     d1 = __ldg(&Ad4[h0 * 2 + 1]);
    float4 d2 = __ldg(&Ad4[h0 * 2 + 2]), d3 = __ldg(&Ad4[h0 * 2 + 3]);
#pragma unroll
    for (int i = 0; i < 4; i++) {
        int n = base + nl + (i << 6);
        if (n < N) {
            float4* zr = (float4*)&g_z1[((size_t)n << 6) + (q << 4)];
            zr[0] = acc[i][0]; zr[1] = acc[i][1];
            zr[2] = acc[i][2]; zr[3] = acc[i][3];
            float as0  = dot4(acc[i][0], s0) + dot4(acc[i][1], s1);
            float as1v = dot4(acc[i][2], s2) + dot4(acc[i][3], s3);
            float ad0  = dot4(acc[i][0], d0) + dot4(acc[i][1], d1);
            float ad1v = dot4(acc[i][2], d2) + dot4(acc[i][3], d3);
            g_as1[n * H1 + h0]     = as0;
            g_as1[n * H1 + h0 + 1] = as1v;
            g_ad1[n * H1 + h0]     = ad0;
            g_ad1[n * H1 + h0 + 1] = ad1v;
            atomicMax(&sMax[h0],         fenc(as0));
            atomicMax(&sMax[h0 + 1],     fenc(as1v));
            atomicMax(&sMax[8 + h0],     fenc(ad0));
            atomicMax(&sMax[8 + h0 + 1], fenc(ad1v));
        }
    }
    __syncthreads();
    if (t < 8)        atomicMax(&g_ms1[t], sMax[t]);
    else if (t < 16)  atomicMax(&g_md1[t - 8], sMax[t]);
}

// ---------------- CSR build ----------------------------------------------------
__global__ void hist_kernel(const int* __restrict__ dst, int E) {
    int i = blockIdx.x * blockDim.x + threadIdx.x;
    int i4 = i << 2;
    if (i4 + 3 < E) {
        int4 d = __ldg((const int4*)dst + i);
        atomicAdd(&g_counts[d.x], 1);
        atomicAdd(&g_counts[d.y], 1);
        atomicAdd(&g_counts[d.z], 1);
        atomicAdd(&g_counts[d.w], 1);
    } else {
        for (int j = i4; j < E && j < i4 + 4; j++)
            atomicAdd(&g_counts[dst[j]], 1);
    }
}

// Phase A: per-block sums of counts (256 elems / block)
__global__ void scanA_kernel(int N) {
    __shared__ int s[256];
    int t = threadIdx.x;
    int i = blockIdx.x * 256 + t;
    s[t] = (i < N) ? g_counts[i] : 0;
    __syncthreads();
#pragma unroll
    for (int off = 128; off > 0; off >>= 1) {
        if (t < off) s[t] += s[t + off];
        __syncthreads();
    }
    if (t == 0) g_bsum[blockIdx.x] = s[0];
}

// Phase C (merged lookback): each block sums g_bsum[0..bid-1] itself, then
// local scan. Also zeroes g_counts for the next call (self-cleaning).
__global__ void scanC_kernel(int N) {
    __shared__ int s[256];
    __shared__ int sbase;
    int t = threadIdx.x;
    int bid = blockIdx.x;
    // warp 0: prefix over prior block sums
    if (t < 32) {
        int sum = 0;
        for (int j = t; j < bid; j += 32) sum += g_bsum[j];
#pragma unroll
        for (int off = 16; off > 0; off >>= 1)
            sum += __shfl_xor_sync(0xffffffffu, sum, off);
        if (t == 0) sbase = sum;
    }
    int i = bid * 256 + t;
    int v = (i < N) ? g_counts[i] : 0;
    if (i < N) g_counts[i] = 0;          // self-clean for next launch
    s[t] = v;
    __syncthreads();
#pragma unroll
    for (int off = 1; off < 256; off <<= 1) {
        int u = (t >= off) ? s[t - off] : 0;
        __syncthreads();
        s[t] += u;
        __syncthreads();
    }
    int incl = s[t];
    int base = sbase;
    if (i < N) {
        int r = base + incl - v;
        g_rowptr[i] = r;
        g_cursor[i] = r;
        if (i == N - 1) g_rowptr[N] = base + incl;
    }
}

__global__ void scatter_kernel(const int* __restrict__ src,
                               const int* __restrict__ dst, int E) {
    int i = blockIdx.x * blockDim.x + threadIdx.x;
    int i4 = i << 2;
    if (i4 + 3 < E) {
        int4 sv = __ldg((const int4*)src + i);
        int4 dv = __ldg((const int4*)dst + i);
        g_csr[atomicAdd(&g_cursor[dv.x], 1)] = sv.x;
        g_csr[atomicAdd(&g_cursor[dv.y], 1)] = sv.y;
        g_csr[atomicAdd(&g_cursor[dv.z], 1)] = sv.z;
        g_csr[atomicAdd(&g_cursor[dv.w], 1)] = sv.w;
    } else {
        for (int j = i4; j < E && j < i4 + 4; j++)
            g_csr[atomicAdd(&g_cursor[dst[j]], 1)] = src[j];
    }
}

// ---------------- fused layer-1 aggregation + layer-2 node transform -----------
// 8 warps/block, 1 node/warp. Phase 1: attention aggregation -> smem h row
// (ELU applied). Phase 2: z2 = h @ W2 from smem, alphas, block-reduced max.
__global__ __launch_bounds__(256)
void agg1n2_kernel(const float* __restrict__ b1,
                   const float* __restrict__ W2,
                   const float* __restrict__ a_src2,
                   const float* __restrict__ a_dst2,
                   int N) {
    __shared__ float sH[8 * 64];
    __shared__ float sW2[64 * 16];
    __shared__ float sA[32];             // a_src2[16], a_dst2[16]
    __shared__ unsigned smS, smD;
    int t = threadIdx.x;
    int wid = t >> 5;
    int lane = t & 31;

    // stage W2 + attention vectors + max slots (no sync needed until phase 2)
    ((float4*)sW2)[t] = __ldg((const float4*)W2 + t);
    if (t < 4)      ((float4*)sA)[t]     = __ldg((const float4*)a_src2 + t);
    else if (t < 8) ((float4*)sA)[t]     = __ldg((const float4*)a_dst2 + (t - 4));
    if (t == 0) { smS = 0u; smD = 0u; }

    int n = (blockIdx.x << 3) + wid;

    // ---------------- phase 1: per-warp GAT aggregation -------------------
    if (n < N) {
        int h8 = lane & 7;
        int grp = lane >> 3;
        int half = lane >> 4;
        int c = lane & 15;
        int hq = c >> 1;

        float ad_rep = g_ad1[n * H1 + h8];
        float M_rep  = fdec(g_ms1[h8]) + fdec(g_md1[h8]);

        float4 acc = make_float4(0.f, 0.f, 0.f, 0.f);
        float den = 0.f;
        int beg = g_rowptr[n], end = g_rowptr[n + 1];

        for (int i = beg; i < end; i += 8) {
            int ea = i + grp, eb = i + 4 + grp;
            bool va = ea < end, vb = eb < end;
            int s_a = va ? __ldg(&g_csr[ea]) : 0;
            int s_b = vb ? __ldg(&g_csr[eb]) : 0;
            float a_a = va ? __ldg(&g_as1[s_a * H1 + h8]) : 0.f;
            float a_b = vb ? __ldg(&g_as1[s_b * H1 + h8]) : 0.f;

            int se0 = __shfl_sync(0xffffffffu, s_a, half << 3);
            int se1 = __shfl_sync(0xffffffffu, s_a, (2 + half) << 3);
            int se2 = __shfl_sync(0xffffffffu, s_b, half << 3);
            int se3 = __shfl_sync(0xffffffffu, s_b, (2 + half) << 3);
            bool v0 = (i + half) < end;
            bool v1 = (i + 2 + half) < end;
            bool v2 = (i + 4 + half) < end;
            bool v3 = (i + 6 + half) < end;
            float4 z0 = v0 ? __ldg((const float4*)&g_z1[((size_t)se0 << 6) + (c << 2)]) : make_float4(0.f,0.f,0.f,0.f);
            float4 z1 = v1 ? __ldg((const float4*)&g_z1[((size_t)se1 << 6) + (c << 2)]) : make_float4(0.f,0.f,0.f,0.f);
            float4 z2 = v2 ? __ldg((const float4*)&g_z1[((size_t)se2 << 6) + (c << 2)]) : make_float4(0.f,0.f,0.f,0.f);
            float4 z3 = v3 ? __ldg((const float4*)&g_z1[((size_t)se3 << 6) + (c << 2)]) : make_float4(0.f,0.f,0.f,0.f);

            float w_a = va ? __expf(leaky(a_a + ad_rep) - M_rep) : 0.f;
            float w_b = vb ? __expf(leaky(a_b + ad_rep) - M_rep) : 0.f;
            den += w_a + w_b;

            float we0 = __shfl_sync(0xffffffffu, w_a, (half << 3) | hq);
            float we1 = __shfl_sync(0xffffffffu, w_a, ((2 + half) << 3) | hq);
            float we2 = __shfl_sync(0xffffffffu, w_b, (half << 3) | hq);
            float we3 = __shfl_sync(0xffffffffu, w_b, ((2 + half) << 3) | hq);

            acc.x += we0 * z0.x + we1 * z1.x + we2 * z2.x + we3 * z3.x;
            acc.y += we0 * z0.y + we1 * z1.y + we2 * z2.y + we3 * z3.y;
            acc.z += we0 * z0.z + we1 * z1.z + we2 * z2.z + we3 * z3.z;
            acc.w += we0 * z0.w + we1 * z1.w + we2 * z2.w + we3 * z3.w;
        }
        acc.x += __shfl_xor_sync(0xffffffffu, acc.x, 16);
        acc.y += __shfl_xor_sync(0xffffffffu, acc.y, 16);
        acc.z += __shfl_xor_sync(0xffffffffu, acc.z, 16);
        acc.w += __shfl_xor_sync(0xffffffffu, acc.w, 16);
        den += __shfl_xor_sync(0xffffffffu, den, 8);
        den += __shfl_xor_sync(0xffffffffu, den, 16);
        float dl = __shfl_sync(0xffffffffu, den, hq);

        if (lane < 16) {
            float4 bb = __ldg((const float4*)&b1[c << 2]);
            float inv = 1.f / (dl + 1e-16f);
            float o0 = acc.x * inv + bb.x;
            float o1 = acc.y * inv + bb.y;
            float o2 = acc.z * inv + bb.z;
            float o3 = acc.w * inv + bb.w;
            o0 = o0 > 0.f ? o0 : (__expf(o0) - 1.f);
            o1 = o1 > 0.f ? o1 : (__expf(o1) - 1.f);
            o2 = o2 > 0.f ? o2 : (__expf(o2) - 1.f);
            o3 = o3 > 0.f ? o3 : (__expf(o3) - 1.f);
            *(float4*)&sH[(wid << 6) + (c << 2)] = make_float4(o0, o1, o2, o3);
        }
    }
    __syncthreads();

    // ---------------- phase 2: z2 = h @ W2, alphas, global max ------------
    // warp wid handles node n; lane = (half<<4)|c : c = output col, half = k half
    {
        int c = lane & 15;
        int half = lane >> 4;
        float acc = 0.f;
        if (n < N) {
            const float* hr = &sH[wid << 6];
#pragma unroll
            for (int kk = 0; kk < 32; kk++) {
                int k = (half << 5) + kk;
                acc += hr[k] * sW2[(k << 4) + c];
            }
        }
        acc += __shfl_xor_sync(0xffffffffu, acc, 16);

        float ts = acc * sA[c];
        float td = acc * sA[16 + c];
#pragma unroll
        for (int off = 8; off > 0; off >>= 1) {
            ts += __shfl_xor_sync(0xffffffffu, ts, off, 16);
            td += __shfl_xor_sync(0xffffffffu, td, off, 16);
        }
        if (n < N) {
            if (lane < 16) g_z2[n * D2 + c] = acc;
            if (lane == 0) {
                g_as2[n] = ts;
                g_ad2[n] = td;
                atomicMax(&smS, fenc(ts));
                atomicMax(&smD, fenc(td));
            }
        }
    }
    __syncthreads();
    if (t == 0) {
        atomicMax(&g_ms2, smS);
        atomicMax(&g_md2, smD);
    }
}

// ---------------- layer-2 aggregation: warp/node, 16 edges per iteration --------
__global__ void agg2_kernel(const float* __restrict__ b2,
                            float* __restrict__ out, int N) {
    int w = (blockIdx.x * blockDim.x + threadIdx.x) >> 5;
    int lane = threadIdx.x & 31;
    if (w >= N) return;
    int n = w;
    int el = lane & 15;
    int g8 = lane >> 2;
    int cq = lane & 3;

    float M2  = fdec(g_ms2) + fdec(g_md2);
    float adl = g_ad2[n];
    float4 acc = make_float4(0.f, 0.f, 0.f, 0.f);
    float den = 0.f;
    int beg = g_rowptr[n], end = g_rowptr[n + 1];

    for (int i = beg; i < end; i += 16) {
        int e = i + el;
        bool v = e < end;
        int s_l = v ? __ldg(&g_csr[e]) : 0;
        float a = v ? __ldg(&g_as2[s_l]) : 0.f;

        int se0 = __shfl_sync(0xffffffffu, s_l, g8);
        int se1 = __shfl_sync(0xffffffffu, s_l, 8 + g8);
        bool v0 = (i + g8) < end;
        bool v1 = (i + 8 + g8) < end;
        float4 z0 = v0 ? __ldg((const float4*)&g_z2[(size_t)se0 * D2 + (cq << 2)]) : make_float4(0.f,0.f,0.f,0.f);
        float4 z1 = v1 ? __ldg((const float4*)&g_z2[(size_t)se1 * D2 + (cq << 2)]) : make_float4(0.f,0.f,0.f,0.f);

        float wv = v ? __expf(leaky(a + adl) - M2) : 0.f;
        if (lane < 16) den += wv;

        float we0 = __shfl_sync(0xffffffffu, wv, g8);
        float we1 = __shfl_sync(0xffffffffu, wv, 8 + g8);
        acc.x += we0 * z0.x + we1 * z1.x;
        acc.y += we0 * z0.y + we1 * z1.y;
        acc.z += we0 * z0.z + we1 * z1.z;
        acc.w += we0 * z0.w + we1 * z1.w;
    }
#pragma unroll
    for (int off = 4; off < 32; off <<= 1) {
        acc.x += __shfl_xor_sync(0xffffffffu, acc.x, off);
        acc.y += __shfl_xor_sync(0xffffffffu, acc.y, off);
        acc.z += __shfl_xor_sync(0xffffffffu, acc.z, off);
        acc.w += __shfl_xor_sync(0xffffffffu, acc.w, off);
    }
    den += __shfl_xor_sync(0xffffffffu, den, 1);
    den += __shfl_xor_sync(0xffffffffu, den, 2);
    den += __shfl_xor_sync(0xffffffffu, den, 4);
    den += __shfl_xor_sync(0xffffffffu, den, 8);
    den = __shfl_sync(0xffffffffu, den, 0);

    if (lane < 4) {
        float4 bb = __ldg((const float4*)&b2[cq << 2]);
        float inv = 1.f / (den + 1e-16f);
        float4 o = make_float4(acc.x * inv + bb.x, acc.y * inv + bb.y,
                               acc.z * inv + bb.z, acc.w * inv + bb.w);
        *(float4*)&out[(size_t)n * D2 + (cq << 2)] = o;
    }
}

// ---------------- launch: forked capture (gemm1 || CSR build) -------------------
static inline int cdiv(int a, int b) { return (a + b - 1) / b; }

extern "C" void kernel_launch(void* const* d_in, const int* in_sizes, int n_in,
                              void* d_out, int out_size) {
    const float* x   = (const float*)d_in[0];
    const int*   ei  = (const int*)d_in[1];
    const float* W1  = (const float*)d_in[2];
    const float* as1 = (const float*)d_in[3];
    const float* ad1 = (const float*)d_in[4];
    const float* b1  = (const float*)d_in[5];
    const float* W2  = (const float*)d_in[6];
    const float* as2 = (const float*)d_in[7];
    const float* ad2 = (const float*)d_in[8];
    const float* b2  = (const float*)d_in[9];
    float* out = (float*)d_out;

    int N = in_sizes[0] / DIN;
    int E = in_sizes[1] / 2;
    const int* src = ei;
    const int* dst = ei + E;
    int NB = cdiv(N, 256);
    int E4 = cdiv(E, 4);

    static cudaStream_t s_side = nullptr;
    static cudaEvent_t ev_fork = nullptr, ev_join = nullptr;
    if (!s_side) {
        cudaStreamCreateWithFlags(&s_side, cudaStreamNonBlocking);
        cudaEventCreateWithFlags(&ev_fork, cudaEventDisableTiming);
        cudaEventCreateWithFlags(&ev_join, cudaEventDisableTiming);
    }

    // fork immediately: CSR branch needs no init (counts self-cleaned)
    cudaEventRecord(ev_fork, 0);
    cudaStreamWaitEvent(s_side, ev_fork, 0);

    // side branch: CSR build
    hist_kernel<<<cdiv(E4, 256), 256, 0, s_side>>>(dst, E);
    scanA_kernel<<<NB, 256, 0, s_side>>>(N);
    scanC_kernel<<<NB, 256, 0, s_side>>>(N);
    scatter_kernel<<<cdiv(E4, 256), 256, 0, s_side>>>(src, dst, E);
    cudaEventRecord(ev_join, s_side);

    // main branch: max-slot init + feature transform
    init_kernel<<<1, 32>>>();
    gemm1_kernel<<<cdiv(N, 256), 256>>>(x, W1, as1, ad1, N);

    // join, then fused aggregation + output
    cudaStreamWaitEvent(0, ev_join, 0);
    agg1n2_kernel<<<cdiv(N, 8), 256>>>(b1, W2, as2, ad2, N);
    agg2_kernel<<<cdiv(N * 32, 256), 256>>>(b2, out, N);
}

// round 6
// speedup vs baseline: 1.0861x; 1.0861x over previous
#include <cuda_runtime.h>
#include <cuda_bf16.h>

// Problem constants (fixed by the dataset)
#define NN 50000
#define EE 850000
#define DIN 128
#define D1 64
#define H1 8
#define D2 16
#define NBMAX 256

// ---------------- scratch (__device__ globals; zero-initialized at load) -------
__device__ float    g_z1[NN * D1];
__device__ float    g_as1[NN * H1];
__device__ float    g_ad1[NN * H1];
__device__ unsigned g_ms1[H1];
__device__ unsigned g_md1[H1];
__device__ int      g_counts[NN];     // self-cleaned by scanC each call
__device__ int      g_rowptr[NN + 1];
__device__ int      g_cursor[NN];
__device__ int      g_csr[EE];
__device__ int      g_bsum[NBMAX];
__device__ float    g_h[NN * D1];
__device__ float    g_z2[NN * D2];
__device__ float    g_as2[NN];
__device__ float    g_ad2[NN];
__device__ unsigned g_ms2;
__device__ unsigned g_md2;

__device__ __forceinline__ unsigned fenc(float f) {
    unsigned u = __float_as_uint(f);
    return (u & 0x80000000u) ? ~u : (u | 0x80000000u);
}
__device__ __forceinline__ float fdec(unsigned u) {
    return __uint_as_float((u & 0x80000000u) ? (u & 0x7fffffffu) : ~u);
}
__device__ __forceinline__ float leaky(float e) { return e > 0.f ? e : 0.2f * e; }
__device__ __forceinline__ float dot4(float4 a, float4 b) {
    return a.x * b.x + a.y * b.y + a.z * b.z + a.w * b.w;
}

// ---------------- init: zero only the max slots (1 warp) -----------------------
__global__ void init_kernel() {
    int i = threadIdx.x;
    if (i < H1) { g_ms1[i] = 0u; g_md1[i] = 0u; }
    if (i == 0) { g_ms2 = 0u; g_md2 = 0u; }
}

// ---------------- GEMM1: 256-node tile, 4 nodes/thread, k-chunked smem ---------
__global__ __launch_bounds__(256, 2)
void gemm1_kernel(const float* __restrict__ x,
                  const float* __restrict__ W1,
                  const float* __restrict__ a_src1,
                  const float* __restrict__ a_dst1,
                  int N) {
    __shared__ float sX[256 * 33];
    __shared__ float sW[32 * 64];
    __shared__ unsigned sMax[16];
    int t = threadIdx.x;
    if (t < 16) sMax[t] = 0u;
    int base = blockIdx.x << 8;
    int nl = t >> 2;
    int q  = t & 3;

    float4 acc[4][4];
#pragma unroll
    for (int i = 0; i < 4; i++)
#pragma unroll
        for (int j = 0; j < 4; j++) acc[i][j] = make_float4(0.f, 0.f, 0.f, 0.f);

    for (int kc = 0; kc < 4; kc++) {
        __syncthreads();
#pragma unroll
        for (int i = 0; i < 2; i++)
            ((float4*)sW)[t + (i << 8)] =
                __ldg((const float4*)(W1 + (kc << 11)) + t + (i << 8));
#pragma unroll
        for (int i = 0; i < 8; i++) {
            int idx = t + (i << 8);
            int node = idx >> 3, k4 = idx & 7;
            int n = base + node;
            float4 v = make_float4(0.f, 0.f, 0.f, 0.f);
            if (n < N) v = __ldg((const float4*)x + ((size_t)n << 5) + (kc << 3) + k4);
            float* dp = &sX[node * 33 + (k4 << 2)];
            dp[0] = v.x; dp[1] = v.y; dp[2] = v.z; dp[3] = v.w;
        }
        __syncthreads();
#pragma unroll 8
        for (int k = 0; k < 32; k++) {
            const float4* wr = (const float4*)&sW[(k << 6) + (q << 4)];
            float4 w0 = wr[0], w1 = wr[1], w2 = wr[2], w3 = wr[3];
#pragma unroll
            for (int i = 0; i < 4; i++) {
                float xv = sX[(nl + (i << 6)) * 33 + k];
                acc[i][0].x += xv * w0.x; acc[i][0].y += xv * w0.y;
                acc[i][0].z += xv * w0.z; acc[i][0].w += xv * w0.w;
                acc[i][1].x += xv * w1.x; acc[i][1].y += xv * w1.y;
                acc[i][1].z += xv * w1.z; acc[i][1].w += xv * w1.w;
                acc[i][2].x += xv * w2.x; acc[i][2].y += xv * w2.y;
                acc[i][2].z += xv * w2.z; acc[i][2].w += xv * w2.w;
                acc[i][3].x += xv * w3.x; acc[i][3].y += xv * w3.y;
                acc[i][3].z += xv * w3.z; acc[i][3].w += xv * w3.w;
            }
        }
    }

    int h0 = q << 1;
    const float4* As4 = (const float4*)a_src1;
    const float4* Ad4 = (const float4*)a_dst1;
    float4 s0 = __ldg(&As4[h0 * 2]),     s1 = __ldg(&As4[h0 * 2 + 1]);
    float4 s2 = __ldg(&As4[h0 * 2 + 2]), s3 = __ldg(&As4[h0 * 2 + 3]);
    float4 d0 = __ldg(&Ad4[h0 * 2]),     d1 = __ldg(&Ad4[h0 * 2 + 1]);
    float4 d2 = __ldg(&Ad4[h0 * 2 + 2]), d3 = __ldg(&Ad4[h0 * 2 + 3]);
#pragma unroll
    for (int i = 0; i < 4; i++) {
        int n = base + nl + (i << 6);
        if (n < N) {
            float4* zr = (float4*)&g_z1[((size_t)n << 6) + (q << 4)];
            zr[0] = acc[i][0]; zr[1] = acc[i][1];
            zr[2] = acc[i][2]; zr[3] = acc[i][3];
            float as0  = dot4(acc[i][0], s0) + dot4(acc[i][1], s1);
            float as1v = dot4(acc[i][2], s2) + dot4(acc[i][3], s3);
            float ad0  = dot4(acc[i][0], d0) + dot4(acc[i][1], d1);
            float ad1v = dot4(acc[i][2], d2) + dot4(acc[i][3], d3);
            g_as1[n * H1 + h0]     = as0;
            g_as1[n * H1 + h0 + 1] = as1v;
            g_ad1[n * H1 + h0]     = ad0;
            g_ad1[n * H1 + h0 + 1] = ad1v;
            atomicMax(&sMax[h0],         fenc(as0));
            atomicMax(&sMax[h0 + 1],     fenc(as1v));
            atomicMax(&sMax[8 + h0],     fenc(ad0));
            atomicMax(&sMax[8 + h0 + 1], fenc(ad1v));
        }
    }
    __syncthreads();
    if (t < 8)        atomicMax(&g_ms1[t], sMax[t]);
    else if (t < 16)  atomicMax(&g_md1[t - 8], sMax[t]);
}

// ---------------- CSR build ----------------------------------------------------
// 2 edges per thread: full chip residency, max outstanding atomics.
__global__ void hist_kernel(const int* __restrict__ dst, int E) {
    int i = blockIdx.x * blockDim.x + threadIdx.x;
    int i2 = i << 1;
    if (i2 + 1 < E) {
        int2 d = __ldg((const int2*)dst + i);
        atomicAdd(&g_counts[d.x], 1);
        atomicAdd(&g_counts[d.y], 1);
    } else if (i2 < E) {
        atomicAdd(&g_counts[dst[i2]], 1);
    }
}

// Phase A: per-block sums of counts (256 elems / block)
__global__ void scanA_kernel(int N) {
    __shared__ int s[256];
    int t = threadIdx.x;
    int i = blockIdx.x * 256 + t;
    s[t] = (i < N) ? g_counts[i] : 0;
    __syncthreads();
#pragma unroll
    for (int off = 128; off > 0; off >>= 1) {
        if (t < off) s[t] += s[t + off];
        __syncthreads();
    }
    if (t == 0) g_bsum[blockIdx.x] = s[0];
}

// Phase C (merged lookback): block sums prior g_bsum entries itself, local scan,
// and zeroes g_counts for the next call (self-cleaning).
__global__ void scanC_kernel(int N) {
    __shared__ int s[256];
    __shared__ int sbase;
    int t = threadIdx.x;
    int bid = blockIdx.x;
    if (t < 32) {
        int sum = 0;
        for (int j = t; j < bid; j += 32) sum += g_bsum[j];
#pragma unroll
        for (int off = 16; off > 0; off >>= 1)
            sum += __shfl_xor_sync(0xffffffffu, sum, off);
        if (t == 0) sbase = sum;
    }
    int i = bid * 256 + t;
    int v = (i < N) ? g_counts[i] : 0;
    if (i < N) g_counts[i] = 0;
    s[t] = v;
    __syncthreads();
#pragma unroll
    for (int off = 1; off < 256; off <<= 1) {
        int u = (t >= off) ? s[t - off] : 0;
        __syncthreads();
        s[t] += u;
        __syncthreads();
    }
    int incl = s[t];
    int base = sbase;
    if (i < N) {
        int r = base + incl - v;
        g_rowptr[i] = r;
        g_cursor[i] = r;
        if (i == N - 1) g_rowptr[N] = base + incl;
    }
}

// 2 edges per thread; issue both atomics before dependent stores.
__global__ void scatter_kernel(const int* __restrict__ src,
                               const int* __restrict__ dst, int E) {
    int i = blockIdx.x * blockDim.x + threadIdx.x;
    int i2 = i << 1;
    if (i2 + 1 < E) {
        int2 sv = __ldg((const int2*)src + i);
        int2 dv = __ldg((const int2*)dst + i);
        int p0 = atomicAdd(&g_cursor[dv.x], 1);
        int p1 = atomicAdd(&g_cursor[dv.y], 1);
        g_csr[p0] = sv.x;
        g_csr[p1] = sv.y;
    } else if (i2 < E) {
        g_csr[atomicAdd(&g_cursor[dst[i2]], 1)] = src[i2];
    }
}

// ---------------- layer-1 aggregation: warp/node, 8 edges per iteration --------
__global__ void agg1_kernel(const float* __restrict__ b1, int N) {
    int w = (blockIdx.x * blockDim.x + threadIdx.x) >> 5;
    int lane = threadIdx.x & 31;
    if (w >= N) return;
    int n = w;
    int h8 = lane & 7;
    int grp = lane >> 3;
    int half = lane >> 4;
    int c = lane & 15;
    int hq = c >> 1;

    float ad_rep = g_ad1[n * H1 + h8];
    float M_rep  = fdec(g_ms1[h8]) + fdec(g_md1[h8]);

    float4 acc = make_float4(0.f, 0.f, 0.f, 0.f);
    float den = 0.f;
    int beg = g_rowptr[n], end = g_rowptr[n + 1];

    for (int i = beg; i < end; i += 8) {
        int ea = i + grp, eb = i + 4 + grp;
        bool va = ea < end, vb = eb < end;
        int s_a = va ? __ldg(&g_csr[ea]) : 0;
        int s_b = vb ? __ldg(&g_csr[eb]) : 0;
        float a_a = va ? __ldg(&g_as1[s_a * H1 + h8]) : 0.f;
        float a_b = vb ? __ldg(&g_as1[s_b * H1 + h8]) : 0.f;

        int se0 = __shfl_sync(0xffffffffu, s_a, half << 3);
        int se1 = __shfl_sync(0xffffffffu, s_a, (2 + half) << 3);
        int se2 = __shfl_sync(0xffffffffu, s_b, half << 3);
        int se3 = __shfl_sync(0xffffffffu, s_b, (2 + half) << 3);
        bool v0 = (i + half) < end;
        bool v1 = (i + 2 + half) < end;
        bool v2 = (i + 4 + half) < end;
        bool v3 = (i + 6 + half) < end;
        float4 z0 = v0 ? __ldg((const float4*)&g_z1[((size_t)se0 << 6) + (c << 2)]) : make_float4(0.f,0.f,0.f,0.f);
        float4 z1 = v1 ? __ldg((const float4*)&g_z1[((size_t)se1 << 6) + (c << 2)]) : make_float4(0.f,0.f,0.f,0.f);
        float4 z2 = v2 ? __ldg((const float4*)&g_z1[((size_t)se2 << 6) + (c << 2)]) : make_float4(0.f,0.f,0.f,0.f);
        float4 z3 = v3 ? __ldg((const float4*)&g_z1[((size_t)se3 << 6) + (c << 2)]) : make_float4(0.f,0.f,0.f,0.f);

        float w_a = va ? __expf(leaky(a_a + ad_rep) - M_rep) : 0.f;
        float w_b = vb ? __expf(leaky(a_b + ad_rep) - M_rep) : 0.f;
        den += w_a + w_b;

        float we0 = __shfl_sync(0xffffffffu, w_a, (half << 3) | hq);
        float we1 = __shfl_sync(0xffffffffu, w_a, ((2 + half) << 3) | hq);
        float we2 = __shfl_sync(0xffffffffu, w_b, (half << 3) | hq);
        float we3 = __shfl_sync(0xffffffffu, w_b, ((2 + half) << 3) | hq);

        acc.x += we0 * z0.x + we1 * z1.x + we2 * z2.x + we3 * z3.x;
        acc.y += we0 * z0.y + we1 * z1.y + we2 * z2.y + we3 * z3.y;
        acc.z += we0 * z0.z + we1 * z1.z + we2 * z2.z + we3 * z3.z;
        acc.w += we0 * z0.w + we1 * z1.w + we2 * z2.w + we3 * z3.w;
    }
    acc.x += __shfl_xor_sync(0xffffffffu, acc.x, 16);
    acc.y += __shfl_xor_sync(0xffffffffu, acc.y, 16);
    acc.z += __shfl_xor_sync(0xffffffffu, acc.z, 16);
    acc.w += __shfl_xor_sync(0xffffffffu, acc.w, 16);
    den += __shfl_xor_sync(0xffffffffu, den, 8);
    den += __shfl_xor_sync(0xffffffffu, den, 16);
    float dl = __shfl_sync(0xffffffffu, den, hq);

    if (lane < 16) {
        float4 bb = __ldg((const float4*)&b1[c << 2]);
        float inv = 1.f / (dl + 1e-16f);
        float o0 = acc.x * inv + bb.x;
        float o1 = acc.y * inv + bb.y;
        float o2 = acc.z * inv + bb.z;
        float o3 = acc.w * inv + bb.w;
        o0 = o0 > 0.f ? o0 : (__expf(o0) - 1.f);
        o1 = o1 > 0.f ? o1 : (__expf(o1) - 1.f);
        o2 = o2 > 0.f ? o2 : (__expf(o2) - 1.f);
        o3 = o3 > 0.f ? o3 : (__expf(o3) - 1.f);
        *(float4*)&g_h[((size_t)n << 6) + (c << 2)] = make_float4(o0, o1, o2, o3);
    }
}

// ---------------- layer-2 node transform (smem-staged) --------------------------
__global__ void node2_kernel(const float* __restrict__ W2,
                             const float* __restrict__ a_src2,
                             const float* __restrict__ a_dst2,
                             int N) {
    __shared__ float sH[16 * 64];
    __shared__ float sW2[64 * 16];
    __shared__ unsigned smS, smD;
    int t = threadIdx.x;
    if (t == 0) { smS = 0u; smD = 0u; }
    int base = blockIdx.x << 4;
    {
        int node = t >> 4, k4 = t & 15;
        int nn = base + node;
        float4 v = make_float4(0.f, 0.f, 0.f, 0.f);
        if (nn < N) v = __ldg((const float4*)&g_h[((size_t)nn << 6) + (k4 << 2)]);
        *(float4*)&sH[(node << 6) + (k4 << 2)] = v;
        ((float4*)sW2)[t] = __ldg((const float4*)W2 + t);
    }
    __syncthreads();

    int nl = t >> 4, c = t & 15;
    int n = base + nl;
    float acc = 0.f;
#pragma unroll 16
    for (int k = 0; k < 64; k++)
        acc += sH[(nl << 6) + k] * sW2[(k << 4) + c];

    float ts = acc * __ldg(&a_src2[c]);
    float td = acc * __ldg(&a_dst2[c]);
#pragma unroll
    for (int off = 8; off > 0; off >>= 1) {
        ts += __shfl_xor_sync(0xffffffffu, ts, off, 16);
        td += __shfl_xor_sync(0xffffffffu, td, off, 16);
    }
    if (n < N) {
        g_z2[n * D2 + c] = acc;
        if (c == 0) {
            g_as2[n] = ts;
            g_ad2[n] = td;
            atomicMax(&smS, fenc(ts));
            atomicMax(&smD, fenc(td));
        }
    }
    __syncthreads();
    if (t == 0) {
        atomicMax(&g_ms2, smS);
        atomicMax(&g_md2, smD);
    }
}

// ---------------- layer-2 aggregation: warp/node, 16 edges per iteration --------
__global__ void agg2_kernel(const float* __restrict__ b2,
                            float* __restrict__ out, int N) {
    int w = (blockIdx.x * blockDim.x + threadIdx.x) >> 5;
    int lane = threadIdx.x & 31;
    if (w >= N) return;
    int n = w;
    int el = lane & 15;
    int g8 = lane >> 2;
    int cq = lane & 3;

    float M2  = fdec(g_ms2) + fdec(g_md2);
    float adl = g_ad2[n];
    float4 acc = make_float4(0.f, 0.f, 0.f, 0.f);
    float den = 0.f;
    int beg = g_rowptr[n], end = g_rowptr[n + 1];

    for (int i = beg; i < end; i += 16) {
        int e = i + el;
        bool v = e < end;
        int s_l = v ? __ldg(&g_csr[e]) : 0;
        float a = v ? __ldg(&g_as2[s_l]) : 0.f;

        int se0 = __shfl_sync(0xffffffffu, s_l, g8);
        int se1 = __shfl_sync(0xffffffffu, s_l, 8 + g8);
        bool v0 = (i + g8) < end;
        bool v1 = (i + 8 + g8) < end;
        float4 z0 = v0 ? __ldg((const float4*)&g_z2[(size_t)se0 * D2 + (cq << 2)]) : make_float4(0.f,0.f,0.f,0.f);
        float4 z1 = v1 ? __ldg((const float4*)&g_z2[(size_t)se1 * D2 + (cq << 2)]) : make_float4(0.f,0.f,0.f,0.f);

        float wv = v ? __expf(leaky(a + adl) - M2) : 0.f;
        if (lane < 16) den += wv;

        float we0 = __shfl_sync(0xffffffffu, wv, g8);
        float we1 = __shfl_sync(0xffffffffu, wv, 8 + g8);
        acc.x += we0 * z0.x + we1 * z1.x;
        acc.y += we0 * z0.y + we1 * z1.y;
        acc.z += we0 * z0.z + we1 * z1.z;
        acc.w += we0 * z0.w + we1 * z1.w;
    }
#pragma unroll
    for (int off = 4; off < 32; off <<= 1) {
        acc.x += __shfl_xor_sync(0xffffffffu, acc.x, off);
        acc.y += __shfl_xor_sync(0xffffffffu, acc.y, off);
        acc.z += __shfl_xor_sync(0xffffffffu, acc.z, off);
        acc.w += __shfl_xor_sync(0xffffffffu, acc.w, off);
    }
    den += __shfl_xor_sync(0xffffffffu, den, 1);
    den += __shfl_xor_sync(0xffffffffu, den, 2);
    den += __shfl_xor_sync(0xffffffffu, den, 4);
    den += __shfl_xor_sync(0xffffffffu, den, 8);
    den = __shfl_sync(0xffffffffu, den, 0);

    if (lane < 4) {
        float4 bb = __ldg((const float4*)&b2[cq << 2]);
        float inv = 1.f / (den + 1e-16f);
        float4 o = make_float4(acc.x * inv + bb.x, acc.y * inv + bb.y,
                               acc.z * inv + bb.z, acc.w * inv + bb.w);
        *(float4*)&out[(size_t)n * D2 + (cq << 2)] = o;
    }
}

// ---------------- launch: forked capture (gemm1 || CSR build) -------------------
static inline int cdiv(int a, int b) { return (a + b - 1) / b; }

extern "C" void kernel_launch(void* const* d_in, const int* in_sizes, int n_in,
                              void* d_out, int out_size) {
    const float* x   = (const float*)d_in[0];
    const int*   ei  = (const int*)d_in[1];
    const float* W1  = (const float*)d_in[2];
    const float* as1 = (const float*)d_in[3];
    const float* ad1 = (const float*)d_in[4];
    const float* b1  = (const float*)d_in[5];
    const float* W2  = (const float*)d_in[6];
    const float* as2 = (const float*)d_in[7];
    const float* ad2 = (const float*)d_in[8];
    const float* b2  = (const float*)d_in[9];
    float* out = (float*)d_out;

    int N = in_sizes[0] / DIN;
    int E = in_sizes[1] / 2;
    const int* src = ei;
    const int* dst = ei + E;
    int NB = cdiv(N, 256);
    int E2 = cdiv(E, 2);

    static cudaStream_t s_side = nullptr;
    static cudaEvent_t ev_fork = nullptr, ev_join = nullptr;
    if (!s_side) {
        cudaStreamCreateWithFlags(&s_side, cudaStreamNonBlocking);
        cudaEventCreateWithFlags(&ev_fork, cudaEventDisableTiming);
        cudaEventCreateWithFlags(&ev_join, cudaEventDisableTiming);
    }

    // fork immediately: CSR branch needs no init (counts self-cleaned)
    cudaEventRecord(ev_fork, 0);
    cudaStreamWaitEvent(s_side, ev_fork, 0);

    // side branch: CSR build
    hist_kernel<<<cdiv(E2, 256), 256, 0, s_side>>>(dst, E);
    scanA_kernel<<<NB, 256, 0, s_side>>>(N);
    scanC_kernel<<<NB, 256, 0, s_side>>>(N);
    scatter_kernel<<<cdiv(E2, 256), 256, 0, s_side>>>(src, dst, E);
    cudaEventRecord(ev_join, s_side);

    // main branch: max-slot init + feature transform
    init_kernel<<<1, 32>>>();
    gemm1_kernel<<<cdiv(N, 256), 256>>>(x, W1, as1, ad1, N);

    // join, then aggregation chain
    cudaStreamWaitEvent(0, ev_join, 0);
    agg1_kernel<<<cdiv(N * 32, 256), 256>>>(b1, N);
    node2_kernel<<<cdiv(N, 16), 256>>>(W2, as2, ad2, N);
    agg2_kernel<<<cdiv(N * 32, 256), 256>>>(b2, out, N);
}